// round 15
// baseline (speedup 1.0000x reference)
#include <cuda_runtime.h>
#include <cuda_bf16.h>
#include <cstddef>

// Problem constants: B=8, C=64, H=W=160, L=25600, Cq=8, GROUPS=4
#define NB 8
#define NC 64
#define NH 160
#define NW 160
#define NL 25600
#define NCQ 8
#define PADQ 162   // qs/ks row pad (floats)
#define PADE 164   // att rows: 656B, 16B aligned
#define PADV 164   // v rows: 656B
#define PADS 68    // [row][c] staging pad (16B-aligned rows for float4 IO)

typedef unsigned long long u64;

__device__ __forceinline__ void ffma2(u64 &d, u64 a, u64 b) {
    asm("fma.rn.f32x2 %0, %1, %2, %0;" : "+l"(d) : "l"(a), "l"(b));
}
__device__ __forceinline__ u64 pack2(float x, float y) {
    u64 u; asm("mov.b64 %0, {%1, %2};" : "=l"(u) : "f"(x), "f"(y)); return u;
}
__device__ __forceinline__ float2 unpack2(u64 u) {
    float2 r; asm("mov.b64 {%0, %1}, %2;" : "=f"(r.x), "=f"(r.y) : "l"(u)); return r;
}

#define REDMAX32(v) { v = fmaxf(v, __shfl_xor_sync(0xffffffffu, v, 1)); \
                      v = fmaxf(v, __shfl_xor_sync(0xffffffffu, v, 2)); \
                      v = fmaxf(v, __shfl_xor_sync(0xffffffffu, v, 4)); \
                      v = fmaxf(v, __shfl_xor_sync(0xffffffffu, v, 8)); \
                      v = fmaxf(v, __shfl_xor_sync(0xffffffffu, v, 16)); }
#define REDSUM32(v) { v += __shfl_xor_sync(0xffffffffu, v, 1); \
                      v += __shfl_xor_sync(0xffffffffu, v, 2); \
                      v += __shfl_xor_sync(0xffffffffu, v, 4); \
                      v += __shfl_xor_sync(0xffffffffu, v, 8); \
                      v += __shfl_xor_sync(0xffffffffu, v, 16); }

// ---------------- scratch ---------------------------------------------------------
__device__ float g_q  [NB*NCQ*NL];        // [b][c][h][w]
__device__ float g_k  [NB*NCQ*NL];
__device__ float g_qT [NB*NCQ*NL];        // [b][w][c][h]
__device__ float g_kT [NB*NCQ*NL];
__device__ float g_v  [NB*NC*NL];         // [b][c][h][w]
__device__ float g_vT [NB*NC*NL];         // [b][w][c][h]
__device__ float g_outH[NB*NH*NW*NC];     // [b][h][w][c]
__device__ float g_o  [NB*NC*NL];         // [b][c][h][w]
__device__ float g_mW [NB*NH*NW];         // [b][h][w]
__device__ float g_sW [NB*NH*NW];
__device__ float g_M  [NB*NW*NH];         // [b][w][h]
__device__ float g_Z  [NB*NW*NH];
__device__ float g_sum[NC], g_sumsq[NC], g_bna[NC], g_bnb[NC];

// ---------------- K1: grouped 1x1 convs q,k,v (float4) + BN-acc zero --------------
__global__ __launch_bounds__(128) void k_qkv(
    const float* __restrict__ x,
    const float* __restrict__ wq, const float* __restrict__ bq,
    const float* __restrict__ wk, const float* __restrict__ bk,
    const float* __restrict__ wv, const float* __restrict__ bv)
{
    __shared__ float swq[128], swk[128], swv[1024], sb[80];
    int t = threadIdx.x;
    if (blockIdx.x == 0 && t < 64) { g_sum[t] = 0.f; g_sumsq[t] = 0.f; }
    for (int i = t; i < 128; i += 128) { swq[i] = wq[i]; swk[i] = wk[i]; }
    for (int i = t; i < 1024; i += 128) swv[i] = wv[i];
    if (t < 8)               sb[t] = bq[t];
    else if (t < 16)         sb[t] = bk[t - 8];
    else if (t < 80)         sb[t] = bv[t - 16];
    __syncthreads();

    int p  = blockIdx.x * 128 + t;
    int b  = p / 6400;
    int q4 = p - b * 6400;
    const float4* xb = (const float4*)(x + (size_t)b * NC * NL) + q4;

    #pragma unroll
    for (int g = 0; g < 4; g++) {
        float4 xr[16];
        #pragma unroll
        for (int c = 0; c < 16; c++) xr[c] = xb[(size_t)(16 * g + c) * 6400];
        #pragma unroll
        for (int o = 0; o < 2; o++) {
            int oc = 2 * g + o;
            float bqv = sb[oc], bkv = sb[8 + oc];
            float4 aq = make_float4(bqv, bqv, bqv, bqv);
            float4 ak = make_float4(bkv, bkv, bkv, bkv);
            #pragma unroll
            for (int c = 0; c < 16; c++) {
                float wqv = swq[oc * 16 + c], wkv = swk[oc * 16 + c];
                aq.x = fmaf(wqv, xr[c].x, aq.x); aq.y = fmaf(wqv, xr[c].y, aq.y);
                aq.z = fmaf(wqv, xr[c].z, aq.z); aq.w = fmaf(wqv, xr[c].w, aq.w);
                ak.x = fmaf(wkv, xr[c].x, ak.x); ak.y = fmaf(wkv, xr[c].y, ak.y);
                ak.z = fmaf(wkv, xr[c].z, ak.z); ak.w = fmaf(wkv, xr[c].w, ak.w);
            }
            ((float4*)g_q)[((size_t)b * NCQ + oc) * 6400 + q4] = aq;
            ((float4*)g_k)[((size_t)b * NCQ + oc) * 6400 + q4] = ak;
        }
        #pragma unroll
        for (int o = 0; o < 16; o++) {
            int oc = 16 * g + o;
            float bv0 = sb[16 + oc];
            float4 av = make_float4(bv0, bv0, bv0, bv0);
            #pragma unroll
            for (int c = 0; c < 16; c++) {
                float wv0 = swv[oc * 16 + c];
                av.x = fmaf(wv0, xr[c].x, av.x); av.y = fmaf(wv0, xr[c].y, av.y);
                av.z = fmaf(wv0, xr[c].z, av.z); av.w = fmaf(wv0, xr[c].w, av.w);
            }
            ((float4*)g_v)[((size_t)b * NC + oc) * 6400 + q4] = av;
        }
    }
}

// ---------------- scalar energy 5x5 (512 thr version, for ewstats) ----------------
__device__ __forceinline__ void energy5x5(
    const float* __restrict__ qs, const float* __restrict__ ks,
    int tx, int ty, int row0, float ef[5][5])
{
    #pragma unroll
    for (int i = 0; i < 5; i++)
        #pragma unroll
        for (int j = 0; j < 5; j++) ef[i][j] = 0.f;
    #pragma unroll
    for (int c = 0; c < NCQ; c++) {
        float qv[5], kv[5];
        #pragma unroll
        for (int ii = 0; ii < 5; ii++) qv[ii] = qs[c * PADQ + row0 + ty * 5 + ii];
        #pragma unroll
        for (int jj = 0; jj < 5; jj++) kv[jj] = ks[c * PADQ + tx + 32 * jj];
        #pragma unroll
        for (int ii = 0; ii < 5; ii++)
            #pragma unroll
            for (int jj = 0; jj < 5; jj++) ef[ii][jj] = fmaf(qv[ii], kv[jj], ef[ii][jj]);
    }
}

// ---------------- K2: per (b,h,half) — energy_W stats (mW, sW) --------------------
__global__ __launch_bounds__(512, 2) void k_ewstats()
{
    __shared__ float qs[NCQ * PADQ], ks[NCQ * PADQ];
    int t = threadIdx.x;
    int bid = blockIdx.x;
    int half = blockIdx.y;
    int b = bid / NH, h = bid - b * NH;
    int row0 = half * 80;

    {
        const float2* gq2 = (const float2*)g_q;
        const float2* gk2 = (const float2*)g_k;
        int base2 = (b * NCQ * NL + h * NW) >> 1;
        for (int i2 = t; i2 < NCQ * 80; i2 += 512) {
            int c = i2 / 80, j2 = i2 - c * 80;
            *(float2*)&qs[c * PADQ + 2 * j2] = gq2[base2 + c * (NL >> 1) + j2];
            *(float2*)&ks[c * PADQ + 2 * j2] = gk2[base2 + c * (NL >> 1) + j2];
        }
    }
    __syncthreads();

    int tx = t & 31, ty = t >> 5;
    float ef[5][5];
    energy5x5(qs, ks, tx, ty, row0, ef);

    #pragma unroll
    for (int ii = 0; ii < 5; ii++) {
        int w = row0 + ty * 5 + ii;
        float m = -3.0e38f;
        #pragma unroll
        for (int jj = 0; jj < 5; jj++) m = fmaxf(m, ef[ii][jj]);
        REDMAX32(m);
        float s = 0.f;
        #pragma unroll
        for (int jj = 0; jj < 5; jj++) s += __expf(ef[ii][jj] - m);
        REDSUM32(s);
        if (tx == 0) {
            g_mW[bid * NW + w] = m;
            g_sW[bid * NW + w] = s;
        }
    }
}

// ---------------- KT: merged tiled transpose, float4 both sides -------------------
__global__ __launch_bounds__(256) void k_transpose_all()
{
    __shared__ float tile[32][36];
    int z = blockIdx.z;
    const float* src; float* dst; int C, bc;
    if (z < 64)       { src = g_q; dst = g_qT; C = 8;  bc = z; }
    else if (z < 128) { src = g_k; dst = g_kT; C = 8;  bc = z - 64; }
    else              { src = g_v; dst = g_vT; C = 64; bc = z - 128; }
    int b = bc / C, c = bc - b * C;
    int w0 = blockIdx.x * 32, h0 = blockIdx.y * 32;
    int t = threadIdx.x;

    {
        int tx = t & 7, ty = t >> 3;
        float4 v4 = *(const float4*)(src + (size_t)bc * NL + (h0 + ty) * NW + w0 + 4 * tx);
        *(float4*)&tile[ty][4 * tx] = v4;
    }
    __syncthreads();
    {
        int hx = t & 7, wy = t >> 3;
        float4 o;
        o.x = tile[4 * hx + 0][wy];
        o.y = tile[4 * hx + 1][wy];
        o.z = tile[4 * hx + 2][wy];
        o.w = tile[4 * hx + 3][wy];
        size_t daddr = ((size_t)b * NW + (w0 + wy)) * (size_t)(C * NH)
                     + (size_t)c * NH + h0 + 4 * hx;
        *(float4*)&dst[daddr] = o;
    }
}

// ---------------- energy 10x5 for 256-thread big kernels --------------------------
// ty8 = t>>5 (0..7): rows ty8*10+ii ; tx = t&31: cols tx+32*jj
__device__ __forceinline__ void energy10x5(
    const float* __restrict__ qs, const float* __restrict__ ks,
    int tx, int ty8, int row0, float ef[10][5])
{
    #pragma unroll
    for (int i = 0; i < 10; i++)
        #pragma unroll
        for (int j = 0; j < 5; j++) ef[i][j] = 0.f;
    #pragma unroll
    for (int c = 0; c < NCQ; c++) {
        float qv[10], kv[5];
        #pragma unroll
        for (int ii = 0; ii < 10; ii++) qv[ii] = qs[c * PADQ + row0 + ty8 * 10 + ii];
        #pragma unroll
        for (int jj = 0; jj < 5; jj++) kv[jj] = ks[c * PADQ + tx + 32 * jj];
        #pragma unroll
        for (int ii = 0; ii < 10; ii++)
            #pragma unroll
            for (int jj = 0; jj < 5; jj++) ef[ii][jj] = fmaf(qv[ii], kv[jj], ef[ii][jj]);
    }
}

// ---------------- attv half (256 thr): warp = 32ch x 20 rows, thread 4c x 5r ------
// c = (warp&1)*32 + (lane&7) + 8a (a<4) ; row = (warp>>1)*20 + (lane>>3)*5 + r
// v loads: 8 distinct chans (656 ≡ 16 mod 128) = 128B, conflict-free
// att loads: 4 distinct rows (5*656 ≡ 80 mod 128), 8-way bcast
__device__ __forceinline__ void attv_half256(
    const float* __restrict__ E, const float* __restrict__ vs,
    int warp, int lane, float out[4][5])
{
    int cb = (warp & 1) * 32 + (lane & 7);
    int hb = (warp >> 1) * 20 + (lane >> 3) * 5;
    u64 acc[4][5];
    #pragma unroll
    for (int a = 0; a < 4; a++)
        #pragma unroll
        for (int r = 0; r < 5; r++) acc[a][r] = 0ull;
    const float* ap = E + hb * PADE;
    const float* vp = vs + cb * PADV;
    #pragma unroll 2
    for (int pq = 0; pq < 40; pq++) {
        u64 a2[5][2], v2[4][2];
        #pragma unroll
        for (int r = 0; r < 5; r++) {
            float4 f = *(const float4*)(ap + r * PADE + 4 * pq);
            a2[r][0] = pack2(f.x, f.y); a2[r][1] = pack2(f.z, f.w);
        }
        #pragma unroll
        for (int a = 0; a < 4; a++) {
            float4 g = *(const float4*)(vp + a * (8 * PADV) + 4 * pq);
            v2[a][0] = pack2(g.x, g.y); v2[a][1] = pack2(g.z, g.w);
        }
        #pragma unroll
        for (int a = 0; a < 4; a++)
            #pragma unroll
            for (int r = 0; r < 5; r++) {
                ffma2(acc[a][r], v2[a][0], a2[r][0]);
                ffma2(acc[a][r], v2[a][1], a2[r][1]);
            }
    }
    #pragma unroll
    for (int a = 0; a < 4; a++)
        #pragma unroll
        for (int r = 0; r < 5; r++) {
            float2 s = unpack2(acc[a][r]);
            out[a][r] = s.x + s.y;
        }
}

// smem layout for half kernels (floats): qs 1296 | ks 1296 | E 80*164 | vs 64*164
#define OFF_KS 1296
#define OFF_E  2592
#define OFF_VS 15712
#define DYN_HALF ((2592 + 80 * PADE + 64 * PADV) * 4)   // 104,832 B

// ---------------- K3a: per (b,w,half) — E_H, joint softmax, att_H, out_H ----------
__global__ __launch_bounds__(256, 2) void k_colpass()
{
    extern __shared__ __align__(16) float sm[];
    float* qs = sm;
    float* ks = sm + OFF_KS;
    float* E  = sm + OFF_E;
    float* vs = sm + OFF_VS;
    int t = threadIdx.x;
    int bidx = blockIdx.x;
    int half = blockIdx.y;
    int b = bidx / NW, w = bidx - b * NW;
    int row0 = half * 80;
    int tx = t & 31, ty8 = t >> 5;

    // prefetch softmax stats before the energy matmul
    float mwr[10], swr[10];
    #pragma unroll
    for (int ii = 0; ii < 10; ii++) {
        int h = row0 + ty8 * 10 + ii;
        mwr[ii] = g_mW[(b * NH + h) * NW + w];
        swr[ii] = g_sW[(b * NH + h) * NW + w];
    }

    {
        const float2* gq2 = (const float2*)g_qT;
        const float2* gk2 = (const float2*)g_kT;
        const float2* gv2 = (const float2*)g_vT;
        int base2 = bidx * 640;
        for (int i2 = t; i2 < 640; i2 += 256) {
            int c = i2 / 80, j2 = i2 - c * 80;
            *(float2*)&qs[c * PADQ + 2 * j2] = gq2[base2 + i2];
            *(float2*)&ks[c * PADQ + 2 * j2] = gk2[base2 + i2];
        }
        int vb2 = bidx * 5120;
        for (int i2 = t; i2 < 5120; i2 += 256) {
            int c = i2 / 80, j2 = i2 - c * 80;
            *(float2*)&vs[c * PADV + 2 * j2] = gv2[vb2 + i2];
        }
    }
    __syncthreads();

    float ef[10][5];
    energy10x5(qs, ks, tx, ty8, row0, ef);

    // joint softmax per global row h (warp-slot owns 10 rows)
    #pragma unroll
    for (int ii = 0; ii < 10; ii++) {
        int hh = ty8 * 10 + ii;
        int h  = row0 + hh;
        float mw = mwr[ii], sw = swr[ii];
        float m = mw;
        #pragma unroll
        for (int jj = 0; jj < 5; jj++) {
            int j = tx + 32 * jj;
            if (j == h) ef[ii][jj] = -1.0e30f;
            m = fmaxf(m, ef[ii][jj]);
        }
        REDMAX32(m);
        float s = 0.f;
        #pragma unroll
        for (int jj = 0; jj < 5; jj++) {
            ef[ii][jj] = __expf(ef[ii][jj] - m);
            s += ef[ii][jj];
        }
        REDSUM32(s);
        float Z = s + sw * __expf(mw - m);
        float inv = 1.f / Z;
        if (tx == 0) {
            g_M[bidx * NH + h] = m;
            g_Z[bidx * NH + h] = Z;
        }
        #pragma unroll
        for (int jj = 0; jj < 5; jj++)
            E[hh * PADE + tx + 32 * jj] = ef[ii][jj] * inv;
    }
    __syncthreads();

    int warp = t >> 5, lane = t & 31;
    float out[4][5];
    attv_half256(E, vs, warp, lane, out);
    __syncthreads();

    // stage [hh][c] (pad 68) then float4 write to g_outH[b][row0+hh][w][c]
    {
        int cb = (warp & 1) * 32 + (lane & 7);
        int hb = (warp >> 1) * 20 + (lane >> 3) * 5;
        #pragma unroll
        for (int a = 0; a < 4; a++)
            #pragma unroll
            for (int r = 0; r < 5; r++)
                E[(hb + r) * PADS + cb + 8 * a] = out[a][r];
    }
    __syncthreads();
    for (int i4 = t; i4 < 80 * 16; i4 += 256) {
        int hh = i4 >> 4, c4 = i4 & 15;
        *(float4*)&g_outH[(((size_t)b * NH + row0 + hh) * NW + w) * NC + 4 * c4] =
            *(float4*)&E[hh * PADS + 4 * c4];
    }
}

// ---------------- K3b: per (b,h,half) — att_W, out_W, combine, conv, BN -----------
__global__ __launch_bounds__(256, 2) void k_rowpass(
    const float* __restrict__ gamma, const float* __restrict__ w1d)
{
    extern __shared__ __align__(16) float sm[];
    __shared__ float sw1[1024];
    __shared__ float csum[NC], csq[NC];
    float* qs = sm;
    float* ks = sm + OFF_KS;
    float* E  = sm + OFF_E;
    float* vs = sm + OFF_VS;
    int t = threadIdx.x;
    int bidx = blockIdx.x;
    int half = blockIdx.y;
    int b = bidx / NH, h = bidx - b * NH;
    int row0 = half * 80;
    int tx = t & 31, ty8 = t >> 5;

    // prefetch joint-softmax stats before the energy matmul
    float Mr[10], Zr[10];
    #pragma unroll
    for (int ii = 0; ii < 10; ii++) {
        int wg = row0 + ty8 * 10 + ii;
        Mr[ii] = g_M[(b * NW + wg) * NH + h];
        Zr[ii] = g_Z[(b * NW + wg) * NH + h];
    }

    for (int i = t; i < 1024; i += 256) sw1[i] = w1d[i];
    if (t < NC) { csum[t] = 0.f; csq[t] = 0.f; }
    {
        const float2* gq2 = (const float2*)g_q;
        const float2* gk2 = (const float2*)g_k;
        const float2* gv2 = (const float2*)g_v;
        int base2 = (b * NCQ * NL + h * NW) >> 1;
        for (int i2 = t; i2 < NCQ * 80; i2 += 256) {
            int c = i2 / 80, j2 = i2 - c * 80;
            *(float2*)&qs[c * PADQ + 2 * j2] = gq2[base2 + c * (NL >> 1) + j2];
            *(float2*)&ks[c * PADQ + 2 * j2] = gk2[base2 + c * (NL >> 1) + j2];
        }
        int vbase2 = (b * NC * NL + h * NW) >> 1;
        for (int i2 = t; i2 < NC * 80; i2 += 256) {
            int c = i2 / 80, j2 = i2 - c * 80;
            *(float2*)&vs[c * PADV + 2 * j2] = gv2[vbase2 + c * (NL >> 1) + j2];
        }
    }
    __syncthreads();

    float ef[10][5];
    energy10x5(qs, ks, tx, ty8, row0, ef);

    // att_W = exp(E_W - M)/Z
    #pragma unroll
    for (int ii = 0; ii < 10; ii++) {
        int wl = ty8 * 10 + ii;
        float M = Mr[ii], Zi = 1.f / Zr[ii];
        #pragma unroll
        for (int jj = 0; jj < 5; jj++)
            E[wl * PADE + tx + 32 * jj] = __expf(ef[ii][jj] - M) * Zi;
    }
    __syncthreads();

    int warp = t >> 5, lane = t & 31;
    float ow[4][5];
    attv_half256(E, vs, warp, lane, ow);
    float gm = gamma[0];
    __syncthreads();

    // load out_H slab for this half's w rows (float4), staged [wl][c] pad 68
    {
        const float4* goh4 = (const float4*)(g_outH + (((size_t)b * NH + h) * NW + row0) * NC);
        for (int i4 = t; i4 < 80 * 16; i4 += 256) {
            int wl = i4 >> 4, c4 = i4 & 15;
            *(float4*)&E[wl * PADS + 4 * c4] = goh4[i4];
        }
    }
    __syncthreads();

    // combine into conv-input vs[c][wl]
    {
        int cb = (warp & 1) * 32 + (lane & 7);
        int hb = (warp >> 1) * 20 + (lane >> 3) * 5;
        #pragma unroll
        for (int a = 0; a < 4; a++)
            #pragma unroll
            for (int r = 0; r < 5; r++) {
                int c = cb + 8 * a, wl = hb + r;
                vs[c * PADV + wl] = gm * (ow[a][r] + E[wl * PADS + c]);
            }
    }
    __syncthreads();

    // grouped conv: oc = t>>2 (64), lane4 = t&3, wl = lane4 + 4k, k<20
    {
        int oc = t >> 2, lane4 = t & 3;
        int g = oc >> 4;
        float s = 0.f, q2 = 0.f;
        #pragma unroll
        for (int k = 0; k < 20; k++) {
            int wl = lane4 + 4 * k;
            float a = 0.f;
            #pragma unroll
            for (int c = 0; c < 16; c++)
                a = fmaf(sw1[oc * 16 + c], vs[(16 * g + c) * PADV + wl], a);
            g_o[((size_t)b * NC + oc) * NL + h * NW + row0 + wl] = a;
            s += a; q2 += a * a;
        }
        s  += __shfl_xor_sync(0xffffffffu, s, 1);  q2 += __shfl_xor_sync(0xffffffffu, q2, 1);
        s  += __shfl_xor_sync(0xffffffffu, s, 2);  q2 += __shfl_xor_sync(0xffffffffu, q2, 2);
        if (lane4 == 0) { atomicAdd(&csum[oc], s); atomicAdd(&csq[oc], q2); }
    }
    __syncthreads();
    if (t < NC) { atomicAdd(&g_sum[t], csum[t]); atomicAdd(&g_sumsq[t], csq[t]); }
}

// ---------------- K4: finalize BN scale/shift -------------------------------------
__global__ void k_bnfin(const float* __restrict__ bn_w, const float* __restrict__ bn_b)
{
    int c = threadIdx.x;
    const float invN = 1.f / (float)(NB * NL);
    float mean = g_sum[c] * invN;
    float var  = g_sumsq[c] * invN - mean * mean;
    float a    = bn_w[c] * rsqrtf(var + 1e-5f);
    g_bna[c] = a;
    g_bnb[c] = bn_b[c] - mean * a;
}

// ---------------- K5: BN apply + residual + ReLU (float4) -------------------------
__global__ __launch_bounds__(256) void k_final(const float* __restrict__ x, float* __restrict__ out)
{
    int i = blockIdx.x * 256 + threadIdx.x;
    int c = (i / 6400) & 63;
    float a = g_bna[c], bb = g_bnb[c];
    float4 o = ((const float4*)g_o)[i];
    float4 xv = ((const float4*)x)[i];
    float4 r;
    r.x = fmaf(o.x, a, bb) + xv.x; r.x = r.x > 0.f ? r.x : 0.f;
    r.y = fmaf(o.y, a, bb) + xv.y; r.y = r.y > 0.f ? r.y : 0.f;
    r.z = fmaf(o.z, a, bb) + xv.z; r.z = r.z > 0.f ? r.z : 0.f;
    r.w = fmaf(o.w, a, bb) + xv.w; r.w = r.w > 0.f ? r.w : 0.f;
    ((float4*)out)[i] = r;
}

// ---------------- host ------------------------------------------------------------
extern "C" void kernel_launch(void* const* d_in, const int* in_sizes, int n_in,
                              void* d_out, int out_size)
{
    (void)in_sizes; (void)n_in; (void)out_size;
    const float* x     = (const float*)d_in[0];
    const float* wq    = (const float*)d_in[1];
    const float* bq    = (const float*)d_in[2];
    const float* wk    = (const float*)d_in[3];
    const float* bk    = (const float*)d_in[4];
    const float* wv    = (const float*)d_in[5];
    const float* bv    = (const float*)d_in[6];
    const float* gamma = (const float*)d_in[7];
    const float* w1d   = (const float*)d_in[8];
    const float* bn_w  = (const float*)d_in[9];
    const float* bn_b  = (const float*)d_in[10];
    float* out = (float*)d_out;

    cudaFuncSetAttribute(k_colpass, cudaFuncAttributeMaxDynamicSharedMemorySize, DYN_HALF);
    cudaFuncSetAttribute(k_rowpass, cudaFuncAttributeMaxDynamicSharedMemorySize, DYN_HALF);

    k_qkv<<<400, 128>>>(x, wq, bq, wk, bk, wv, bv);                 // 0
    k_ewstats<<<dim3(NB * NH, 2), 512>>>();                         // 1
    k_transpose_all<<<dim3(5, 5, 640), 256>>>();                    // 2
    k_colpass<<<dim3(NB * NW, 2), 256, DYN_HALF>>>();               // 3
    k_rowpass<<<dim3(NB * NH, 2), 256, DYN_HALF>>>(gamma, w1d);     // 4
    k_bnfin<<<1, 64>>>(bn_w, bn_b);                                 // 5
    k_final<<<(NB * NC * NL) / 1024, 256>>>(x, out);                // 6
}

// round 16
// speedup vs baseline: 1.1560x; 1.1560x over previous
#include <cuda_runtime.h>
#include <cuda_bf16.h>
#include <cstddef>

// Problem constants: B=8, C=64, H=W=160, L=25600, Cq=8, GROUPS=4
#define NB 8
#define NC 64
#define NH 160
#define NW 160
#define NL 25600
#define NCQ 8
#define PADQ 162   // qs/ks row pad (floats)
#define PADE 164   // att rows: 656B, 16B aligned
#define PADV 164   // v rows: 656B
#define PADS 68    // [row][c] staging pad (16B-aligned rows for float4 IO)

typedef unsigned long long u64;

__device__ __forceinline__ void ffma2(u64 &d, u64 a, u64 b) {
    asm("fma.rn.f32x2 %0, %1, %2, %0;" : "+l"(d) : "l"(a), "l"(b));
}
__device__ __forceinline__ u64 pack2(float x, float y) {
    u64 u; asm("mov.b64 %0, {%1, %2};" : "=l"(u) : "f"(x), "f"(y)); return u;
}
__device__ __forceinline__ float2 unpack2(u64 u) {
    float2 r; asm("mov.b64 {%0, %1}, %2;" : "=f"(r.x), "=f"(r.y) : "l"(u)); return r;
}

#define REDMAX32(v) { v = fmaxf(v, __shfl_xor_sync(0xffffffffu, v, 1)); \
                      v = fmaxf(v, __shfl_xor_sync(0xffffffffu, v, 2)); \
                      v = fmaxf(v, __shfl_xor_sync(0xffffffffu, v, 4)); \
                      v = fmaxf(v, __shfl_xor_sync(0xffffffffu, v, 8)); \
                      v = fmaxf(v, __shfl_xor_sync(0xffffffffu, v, 16)); }
#define REDSUM32(v) { v += __shfl_xor_sync(0xffffffffu, v, 1); \
                      v += __shfl_xor_sync(0xffffffffu, v, 2); \
                      v += __shfl_xor_sync(0xffffffffu, v, 4); \
                      v += __shfl_xor_sync(0xffffffffu, v, 8); \
                      v += __shfl_xor_sync(0xffffffffu, v, 16); }

// ---------------- scratch ---------------------------------------------------------
__device__ float g_q  [NB*NCQ*NL];        // [b][c][h][w]
__device__ float g_k  [NB*NCQ*NL];
__device__ float g_qT [NB*NCQ*NL];        // [b][w][c][h]
__device__ float g_kT [NB*NCQ*NL];
__device__ float g_v  [NB*NC*NL];         // [b][c][h][w]
__device__ float g_vT [NB*NC*NL];         // [b][w][c][h]
__device__ float g_outH[NB*NH*NW*NC];     // [b][h][w][c], UNNORMALIZED out_H~
__device__ float g_o  [NB*NC*NL];         // [b][c][h][w]
__device__ float g_mH [NB*NW*NH];         // [b][w][h] local E_H row max
__device__ float g_sH [NB*NW*NH];         // [b][w][h] local E_H row sum
__device__ float g_sum[NC], g_sumsq[NC], g_bna[NC], g_bnb[NC];

// ---------------- K1: grouped 1x1 convs q,k,v (float4) + BN-acc zero --------------
__global__ __launch_bounds__(128) void k_qkv(
    const float* __restrict__ x,
    const float* __restrict__ wq, const float* __restrict__ bq,
    const float* __restrict__ wk, const float* __restrict__ bk,
    const float* __restrict__ wv, const float* __restrict__ bv)
{
    __shared__ float swq[128], swk[128], swv[1024], sb[80];
    int t = threadIdx.x;
    if (blockIdx.x == 0 && t < 64) { g_sum[t] = 0.f; g_sumsq[t] = 0.f; }
    for (int i = t; i < 128; i += 128) { swq[i] = wq[i]; swk[i] = wk[i]; }
    for (int i = t; i < 1024; i += 128) swv[i] = wv[i];
    if (t < 8)               sb[t] = bq[t];
    else if (t < 16)         sb[t] = bk[t - 8];
    else if (t < 80)         sb[t] = bv[t - 16];
    __syncthreads();

    int p  = blockIdx.x * 128 + t;
    int b  = p / 6400;
    int q4 = p - b * 6400;
    const float4* xb = (const float4*)(x + (size_t)b * NC * NL) + q4;

    #pragma unroll
    for (int g = 0; g < 4; g++) {
        float4 xr[16];
        #pragma unroll
        for (int c = 0; c < 16; c++) xr[c] = xb[(size_t)(16 * g + c) * 6400];
        #pragma unroll
        for (int o = 0; o < 2; o++) {
            int oc = 2 * g + o;
            float bqv = sb[oc], bkv = sb[8 + oc];
            float4 aq = make_float4(bqv, bqv, bqv, bqv);
            float4 ak = make_float4(bkv, bkv, bkv, bkv);
            #pragma unroll
            for (int c = 0; c < 16; c++) {
                float wqv = swq[oc * 16 + c], wkv = swk[oc * 16 + c];
                aq.x = fmaf(wqv, xr[c].x, aq.x); aq.y = fmaf(wqv, xr[c].y, aq.y);
                aq.z = fmaf(wqv, xr[c].z, aq.z); aq.w = fmaf(wqv, xr[c].w, aq.w);
                ak.x = fmaf(wkv, xr[c].x, ak.x); ak.y = fmaf(wkv, xr[c].y, ak.y);
                ak.z = fmaf(wkv, xr[c].z, ak.z); ak.w = fmaf(wkv, xr[c].w, ak.w);
            }
            ((float4*)g_q)[((size_t)b * NCQ + oc) * 6400 + q4] = aq;
            ((float4*)g_k)[((size_t)b * NCQ + oc) * 6400 + q4] = ak;
        }
        #pragma unroll
        for (int o = 0; o < 16; o++) {
            int oc = 16 * g + o;
            float bv0 = sb[16 + oc];
            float4 av = make_float4(bv0, bv0, bv0, bv0);
            #pragma unroll
            for (int c = 0; c < 16; c++) {
                float wv0 = swv[oc * 16 + c];
                av.x = fmaf(wv0, xr[c].x, av.x); av.y = fmaf(wv0, xr[c].y, av.y);
                av.z = fmaf(wv0, xr[c].z, av.z); av.w = fmaf(wv0, xr[c].w, av.w);
            }
            ((float4*)g_v)[((size_t)b * NC + oc) * 6400 + q4] = av;
        }
    }
}

// ---------------- KT: merged tiled transpose, float4 both sides -------------------
__global__ __launch_bounds__(256) void k_transpose_all()
{
    __shared__ float tile[32][36];
    int z = blockIdx.z;
    const float* src; float* dst; int C, bc;
    if (z < 64)       { src = g_q; dst = g_qT; C = 8;  bc = z; }
    else if (z < 128) { src = g_k; dst = g_kT; C = 8;  bc = z - 64; }
    else              { src = g_v; dst = g_vT; C = 64; bc = z - 128; }
    int b = bc / C, c = bc - b * C;
    int w0 = blockIdx.x * 32, h0 = blockIdx.y * 32;
    int t = threadIdx.x;

    {
        int tx = t & 7, ty = t >> 3;
        float4 v4 = *(const float4*)(src + (size_t)bc * NL + (h0 + ty) * NW + w0 + 4 * tx);
        *(float4*)&tile[ty][4 * tx] = v4;
    }
    __syncthreads();
    {
        int hx = t & 7, wy = t >> 3;
        float4 o;
        o.x = tile[4 * hx + 0][wy];
        o.y = tile[4 * hx + 1][wy];
        o.z = tile[4 * hx + 2][wy];
        o.w = tile[4 * hx + 3][wy];
        size_t daddr = ((size_t)b * NW + (w0 + wy)) * (size_t)(C * NH)
                     + (size_t)c * NH + h0 + 4 * hx;
        *(float4*)&dst[daddr] = o;
    }
}

// ---------------- scalar energy 5x5 (512 thr, 80 rows x 160 cols) -----------------
__device__ __forceinline__ void energy5x5(
    const float* __restrict__ qs, const float* __restrict__ ks,
    int tx, int ty, int row0, float ef[5][5])
{
    #pragma unroll
    for (int i = 0; i < 5; i++)
        #pragma unroll
        for (int j = 0; j < 5; j++) ef[i][j] = 0.f;
    #pragma unroll
    for (int c = 0; c < NCQ; c++) {
        float qv[5], kv[5];
        #pragma unroll
        for (int ii = 0; ii < 5; ii++) qv[ii] = qs[c * PADQ + row0 + ty * 5 + ii];
        #pragma unroll
        for (int jj = 0; jj < 5; jj++) kv[jj] = ks[c * PADQ + tx + 32 * jj];
        #pragma unroll
        for (int ii = 0; ii < 5; ii++)
            #pragma unroll
            for (int jj = 0; jj < 5; jj++) ef[ii][jj] = fmaf(qv[ii], kv[jj], ef[ii][jj]);
    }
}

// ---------------- attv half: 80 rows, warp = 16ch x 20 rows, thread 2c x 5r -------
__device__ __forceinline__ void attv_half(
    const float* __restrict__ E, const float* __restrict__ vs,
    int warp, int lane, float out[2][5])
{
    int cb = (warp & 3) * 16 + (lane & 7);
    int hb = (warp >> 2) * 20 + (lane >> 3) * 5;
    u64 acc[2][5];
    #pragma unroll
    for (int a = 0; a < 2; a++)
        #pragma unroll
        for (int r = 0; r < 5; r++) acc[a][r] = 0ull;
    const float* ap = E + hb * PADE;
    const float* vp = vs + cb * PADV;
    #pragma unroll 2
    for (int pq = 0; pq < 40; pq++) {
        u64 a2[5][2], v2[2][2];
        #pragma unroll
        for (int r = 0; r < 5; r++) {
            float4 f = *(const float4*)(ap + r * PADE + 4 * pq);
            a2[r][0] = pack2(f.x, f.y); a2[r][1] = pack2(f.z, f.w);
        }
        #pragma unroll
        for (int a = 0; a < 2; a++) {
            float4 g = *(const float4*)(vp + a * (8 * PADV) + 4 * pq);
            v2[a][0] = pack2(g.x, g.y); v2[a][1] = pack2(g.z, g.w);
        }
        #pragma unroll
        for (int a = 0; a < 2; a++)
            #pragma unroll
            for (int r = 0; r < 5; r++) {
                ffma2(acc[a][r], v2[a][0], a2[r][0]);
                ffma2(acc[a][r], v2[a][1], a2[r][1]);
            }
    }
    #pragma unroll
    for (int a = 0; a < 2; a++)
        #pragma unroll
        for (int r = 0; r < 5; r++) {
            float2 s = unpack2(acc[a][r]);
            out[a][r] = s.x + s.y;
        }
}

// smem layout for half kernels (floats): qs 1296 | ks 1296 | E 80*164 | vs 64*164
#define OFF_KS 1296
#define OFF_E  2592
#define OFF_VS 15712
#define DYN_HALF ((2592 + 80 * PADE + 64 * PADV) * 4)   // 104,832 B

// ---------------- K3a: per (b,w,half) — E_H, LOCAL softmax, att_H~, out_H~ --------
__global__ __launch_bounds__(512, 2) void k_colpass()
{
    extern __shared__ __align__(16) float sm[];
    float* qs = sm;
    float* ks = sm + OFF_KS;
    float* E  = sm + OFF_E;
    float* vs = sm + OFF_VS;
    int t = threadIdx.x;
    int bidx = blockIdx.x;
    int half = blockIdx.y;
    int b = bidx / NW, w = bidx - b * NW;
    int row0 = half * 80;
    int tx = t & 31, ty = t >> 5;

    {
        const float2* gq2 = (const float2*)g_qT;
        const float2* gk2 = (const float2*)g_kT;
        const float2* gv2 = (const float2*)g_vT;
        int base2 = bidx * 640;
        for (int i2 = t; i2 < 640; i2 += 512) {
            int c = i2 / 80, j2 = i2 - c * 80;
            *(float2*)&qs[c * PADQ + 2 * j2] = gq2[base2 + i2];
            *(float2*)&ks[c * PADQ + 2 * j2] = gk2[base2 + i2];
        }
        int vb2 = bidx * 5120;
        for (int i2 = t; i2 < 5120; i2 += 512) {
            int c = i2 / 80, j2 = i2 - c * 80;
            *(float2*)&vs[c * PADV + 2 * j2] = gv2[vb2 + i2];
        }
    }
    __syncthreads();

    float ef[5][5];
    energy5x5(qs, ks, tx, ty, row0, ef);

    // LOCAL softmax per row h: mask diag, compute (mH, sH), write exp(e-mH) UNNORMALIZED
    #pragma unroll
    for (int ii = 0; ii < 5; ii++) {
        int hh = ty * 5 + ii;
        int h  = row0 + hh;
        float m = -3.0e38f;
        #pragma unroll
        for (int jj = 0; jj < 5; jj++) {
            int j = tx + 32 * jj;
            if (j == h) ef[ii][jj] = -1.0e30f;
            m = fmaxf(m, ef[ii][jj]);
        }
        REDMAX32(m);
        float s = 0.f;
        #pragma unroll
        for (int jj = 0; jj < 5; jj++) {
            ef[ii][jj] = __expf(ef[ii][jj] - m);
            s += ef[ii][jj];
        }
        REDSUM32(s);
        if (tx == 0) {
            g_mH[bidx * NH + h] = m;
            g_sH[bidx * NH + h] = s;
        }
        #pragma unroll
        for (int jj = 0; jj < 5; jj++)
            E[hh * PADE + tx + 32 * jj] = ef[ii][jj];
    }
    __syncthreads();

    int warp = t >> 5, lane = t & 31;
    float out[2][5];
    attv_half(E, vs, warp, lane, out);
    __syncthreads();

    // stage [hh][c] (pad 68) then float4 write to g_outH[b][row0+hh][w][c]
    {
        int cb = (warp & 3) * 16 + (lane & 7);
        int hb = (warp >> 2) * 20 + (lane >> 3) * 5;
        #pragma unroll
        for (int a = 0; a < 2; a++)
            #pragma unroll
            for (int r = 0; r < 5; r++)
                E[(hb + r) * PADS + cb + 8 * a] = out[a][r];
    }
    __syncthreads();
    for (int i4 = t; i4 < 80 * 16; i4 += 512) {
        int hh = i4 >> 4, c4 = i4 & 15;
        *(float4*)&g_outH[(((size_t)b * NH + row0 + hh) * NW + w) * NC + 4 * c4] =
            *(float4*)&E[hh * PADS + 4 * c4];
    }
}

// ---------------- K3b: per (b,h,half) — E_W, local stats, merge, conv, BN ---------
__global__ __launch_bounds__(512, 2) void k_rowpass(
    const float* __restrict__ gamma, const float* __restrict__ w1d)
{
    extern __shared__ __align__(16) float sm[];
    __shared__ float sw1[1024];
    __shared__ float csum[NC], csq[NC];
    __shared__ float scH[80], scW[80];     // per-wl combine scales
    float* qs = sm;
    float* ks = sm + OFF_KS;
    float* E  = sm + OFF_E;
    float* vs = sm + OFF_VS;
    int t = threadIdx.x;
    int bidx = blockIdx.x;
    int half = blockIdx.y;
    int b = bidx / NH, h = bidx - b * NH;
    int row0 = half * 80;
    int tx = t & 31, ty = t >> 5;

    // prefetch colpass local stats (broadcast loads) before the energy matmul
    float mHr[5], sHr[5];
    #pragma unroll
    for (int ii = 0; ii < 5; ii++) {
        int wg = row0 + ty * 5 + ii;
        mHr[ii] = g_mH[(b * NW + wg) * NH + h];
        sHr[ii] = g_sH[(b * NW + wg) * NH + h];
    }

    for (int i = t; i < 1024; i += 512) sw1[i] = w1d[i];
    if (t < NC) { csum[t] = 0.f; csq[t] = 0.f; }
    {
        const float2* gq2 = (const float2*)g_q;
        const float2* gk2 = (const float2*)g_k;
        const float2* gv2 = (const float2*)g_v;
        int base2 = (b * NCQ * NL + h * NW) >> 1;
        for (int i2 = t; i2 < NCQ * 80; i2 += 512) {
            int c = i2 / 80, j2 = i2 - c * 80;
            *(float2*)&qs[c * PADQ + 2 * j2] = gq2[base2 + c * (NL >> 1) + j2];
            *(float2*)&ks[c * PADQ + 2 * j2] = gk2[base2 + c * (NL >> 1) + j2];
        }
        int vbase2 = (b * NC * NL + h * NW) >> 1;
        for (int i2 = t; i2 < NC * 80; i2 += 512) {
            int c = i2 / 80, j2 = i2 - c * 80;
            *(float2*)&vs[c * PADV + 2 * j2] = gv2[vbase2 + c * (NL >> 1) + j2];
        }
    }
    __syncthreads();

    float ef[5][5];
    energy5x5(qs, ks, tx, ty, row0, ef);

    // local E_W stats per row wl, merge with (mH, sH), write exp(e-mW) unnormalized
    #pragma unroll
    for (int ii = 0; ii < 5; ii++) {
        int wl = ty * 5 + ii;
        float m = -3.0e38f;
        #pragma unroll
        for (int jj = 0; jj < 5; jj++) m = fmaxf(m, ef[ii][jj]);
        REDMAX32(m);
        float s = 0.f;
        #pragma unroll
        for (int jj = 0; jj < 5; jj++) {
            ef[ii][jj] = __expf(ef[ii][jj] - m);
            s += ef[ii][jj];
        }
        REDSUM32(s);
        if (tx == 0) {
            float mH = mHr[ii], sH = sHr[ii];
            float M  = fmaxf(mH, m);
            float aH = __expf(mH - M), aW = __expf(m - M);
            float Zi = 1.f / (sH * aH + s * aW);
            scH[wl] = aH * Zi;
            scW[wl] = aW * Zi;
        }
        #pragma unroll
        for (int jj = 0; jj < 5; jj++)
            E[wl * PADE + tx + 32 * jj] = ef[ii][jj];
    }
    __syncthreads();

    int warp = t >> 5, lane = t & 31;
    float ow[2][5];
    attv_half(E, vs, warp, lane, ow);
    float gm = gamma[0];
    __syncthreads();

    // load out_H~ slab for this half's w rows (float4), staged [wl][c] pad 68
    {
        const float4* goh4 = (const float4*)(g_outH + (((size_t)b * NH + h) * NW + row0) * NC);
        for (int i4 = t; i4 < 80 * 16; i4 += 512) {
            int wl = i4 >> 4, c4 = i4 & 15;
            *(float4*)&E[wl * PADS + 4 * c4] = goh4[i4];
        }
    }
    __syncthreads();

    // combine into conv-input vs[c][wl]: gamma*(out_W~*scW + out_H~*scH)
    {
        int cb = (warp & 3) * 16 + (lane & 7);
        int hb = (warp >> 2) * 20 + (lane >> 3) * 5;
        #pragma unroll
        for (int a = 0; a < 2; a++)
            #pragma unroll
            for (int r = 0; r < 5; r++) {
                int c = cb + 8 * a, wl = hb + r;
                vs[c * PADV + wl] = gm * (ow[a][r] * scW[wl] + E[wl * PADS + c] * scH[wl]);
            }
    }
    __syncthreads();

    // grouped conv: oc = t>>3 (64), lane8 = t&7, wl = lane8 + 8k, k<10
    {
        int oc = t >> 3, lane8 = t & 7;
        int g = oc >> 4;
        float s = 0.f, q2 = 0.f;
        #pragma unroll
        for (int k = 0; k < 10; k++) {
            int wl = lane8 + 8 * k;
            float a = 0.f;
            #pragma unroll
            for (int c = 0; c < 16; c++)
                a = fmaf(sw1[oc * 16 + c], vs[(16 * g + c) * PADV + wl], a);
            g_o[((size_t)b * NC + oc) * NL + h * NW + row0 + wl] = a;
            s += a; q2 += a * a;
        }
        s  += __shfl_xor_sync(0xffffffffu, s, 1);  q2 += __shfl_xor_sync(0xffffffffu, q2, 1);
        s  += __shfl_xor_sync(0xffffffffu, s, 2);  q2 += __shfl_xor_sync(0xffffffffu, q2, 2);
        s  += __shfl_xor_sync(0xffffffffu, s, 4);  q2 += __shfl_xor_sync(0xffffffffu, q2, 4);
        if (lane8 == 0) { atomicAdd(&csum[oc], s); atomicAdd(&csq[oc], q2); }
    }
    __syncthreads();
    if (t < NC) { atomicAdd(&g_sum[t], csum[t]); atomicAdd(&g_sumsq[t], csq[t]); }
}

// ---------------- K4: finalize BN scale/shift -------------------------------------
__global__ void k_bnfin(const float* __restrict__ bn_w, const float* __restrict__ bn_b)
{
    int c = threadIdx.x;
    const float invN = 1.f / (float)(NB * NL);
    float mean = g_sum[c] * invN;
    float var  = g_sumsq[c] * invN - mean * mean;
    float a    = bn_w[c] * rsqrtf(var + 1e-5f);
    g_bna[c] = a;
    g_bnb[c] = bn_b[c] - mean * a;
}

// ---------------- K5: BN apply + residual + ReLU (float4) -------------------------
__global__ __launch_bounds__(256) void k_final(const float* __restrict__ x, float* __restrict__ out)
{
    int i = blockIdx.x * 256 + threadIdx.x;
    int c = (i / 6400) & 63;
    float a = g_bna[c], bb = g_bnb[c];
    float4 o = ((const float4*)g_o)[i];
    float4 xv = ((const float4*)x)[i];
    float4 r;
    r.x = fmaf(o.x, a, bb) + xv.x; r.x = r.x > 0.f ? r.x : 0.f;
    r.y = fmaf(o.y, a, bb) + xv.y; r.y = r.y > 0.f ? r.y : 0.f;
    r.z = fmaf(o.z, a, bb) + xv.z; r.z = r.z > 0.f ? r.z : 0.f;
    r.w = fmaf(o.w, a, bb) + xv.w; r.w = r.w > 0.f ? r.w : 0.f;
    ((float4*)out)[i] = r;
}

// ---------------- host ------------------------------------------------------------
extern "C" void kernel_launch(void* const* d_in, const int* in_sizes, int n_in,
                              void* d_out, int out_size)
{
    (void)in_sizes; (void)n_in; (void)out_size;
    const float* x     = (const float*)d_in[0];
    const float* wq    = (const float*)d_in[1];
    const float* bq    = (const float*)d_in[2];
    const float* wk    = (const float*)d_in[3];
    const float* bk    = (const float*)d_in[4];
    const float* wv    = (const float*)d_in[5];
    const float* bv    = (const float*)d_in[6];
    const float* gamma = (const float*)d_in[7];
    const float* w1d   = (const float*)d_in[8];
    const float* bn_w  = (const float*)d_in[9];
    const float* bn_b  = (const float*)d_in[10];
    float* out = (float*)d_out;

    cudaFuncSetAttribute(k_colpass, cudaFuncAttributeMaxDynamicSharedMemorySize, DYN_HALF);
    cudaFuncSetAttribute(k_rowpass, cudaFuncAttributeMaxDynamicSharedMemorySize, DYN_HALF);

    k_qkv<<<400, 128>>>(x, wq, bq, wk, bk, wv, bv);                 // 0
    k_transpose_all<<<dim3(5, 5, 640), 256>>>();                    // 1
    k_colpass<<<dim3(NB * NW, 2), 512, DYN_HALF>>>();               // 2
    k_rowpass<<<dim3(NB * NH, 2), 512, DYN_HALF>>>(gamma, w1d);     // 3
    k_bnfin<<<1, 64>>>(bn_w, bn_b);                                 // 4
    k_final<<<(NB * NC * NL) / 1024, 256>>>(x, out);                // 5
}

// round 17
// speedup vs baseline: 1.2185x; 1.0541x over previous
#include <cuda_runtime.h>
#include <cuda_bf16.h>
#include <cstddef>

// Problem constants: B=8, C=64, H=W=160, L=25600, Cq=8, GROUPS=4
#define NB 8
#define NC 64
#define NH 160
#define NW 160
#define NL 25600
#define NCQ 8
#define PADQ 162   // qs/ks row pad (floats)
#define PADE 164   // att rows: 656B, 16B aligned
#define PADV 164   // v rows: 656B
#define PADS 68    // [row][c] staging pad (16B-aligned rows for float4 IO)

typedef unsigned long long u64;

__device__ __forceinline__ void ffma2(u64 &d, u64 a, u64 b) {
    asm("fma.rn.f32x2 %0, %1, %2, %0;" : "+l"(d) : "l"(a), "l"(b));
}
__device__ __forceinline__ u64 pack2(float x, float y) {
    u64 u; asm("mov.b64 %0, {%1, %2};" : "=l"(u) : "f"(x), "f"(y)); return u;
}
__device__ __forceinline__ float2 unpack2(u64 u) {
    float2 r; asm("mov.b64 {%0, %1}, %2;" : "=f"(r.x), "=f"(r.y) : "l"(u)); return r;
}

#define REDMAX32(v) { v = fmaxf(v, __shfl_xor_sync(0xffffffffu, v, 1)); \
                      v = fmaxf(v, __shfl_xor_sync(0xffffffffu, v, 2)); \
                      v = fmaxf(v, __shfl_xor_sync(0xffffffffu, v, 4)); \
                      v = fmaxf(v, __shfl_xor_sync(0xffffffffu, v, 8)); \
                      v = fmaxf(v, __shfl_xor_sync(0xffffffffu, v, 16)); }
#define REDSUM32(v) { v += __shfl_xor_sync(0xffffffffu, v, 1); \
                      v += __shfl_xor_sync(0xffffffffu, v, 2); \
                      v += __shfl_xor_sync(0xffffffffu, v, 4); \
                      v += __shfl_xor_sync(0xffffffffu, v, 8); \
                      v += __shfl_xor_sync(0xffffffffu, v, 16); }

// ---------------- scratch ---------------------------------------------------------
__device__ float g_q  [NB*NCQ*NL];        // [b][c][h][w]
__device__ float g_k  [NB*NCQ*NL];
__device__ float g_qT [NB*NCQ*NL];        // [b][w][c][h]
__device__ float g_kT [NB*NCQ*NL];
__device__ float g_v  [NB*NC*NL];         // [b][c][h][w]
__device__ float g_vT [NB*NC*NL];         // [b][w][c][h]
__device__ float g_outH[NB*NH*NW*NC];     // [b][h][w][c], UNNORMALIZED out_H~
__device__ float g_o  [NB*NC*NL];         // [b][c][h][w]
__device__ float g_mH [NB*NW*NH];         // [b][w][h] local E_H row max
__device__ float g_sH [NB*NW*NH];         // [b][w][h] local E_H row sum
__device__ float g_sum[NC], g_sumsq[NC], g_bna[NC], g_bnb[NC];

// ---------------- K1: grouped 1x1 convs q,k,v (float4) + BN-acc zero --------------
__global__ __launch_bounds__(128) void k_qkv(
    const float* __restrict__ x,
    const float* __restrict__ wq, const float* __restrict__ bq,
    const float* __restrict__ wk, const float* __restrict__ bk,
    const float* __restrict__ wv, const float* __restrict__ bv)
{
    __shared__ float swq[128], swk[128], swv[1024], sb[80];
    int t = threadIdx.x;
    if (blockIdx.x == 0 && t < 64) { g_sum[t] = 0.f; g_sumsq[t] = 0.f; }
    for (int i = t; i < 128; i += 128) { swq[i] = wq[i]; swk[i] = wk[i]; }
    for (int i = t; i < 1024; i += 128) swv[i] = wv[i];
    if (t < 8)               sb[t] = bq[t];
    else if (t < 16)         sb[t] = bk[t - 8];
    else if (t < 80)         sb[t] = bv[t - 16];
    __syncthreads();

    int p  = blockIdx.x * 128 + t;
    int b  = p / 6400;
    int q4 = p - b * 6400;
    const float4* xb = (const float4*)(x + (size_t)b * NC * NL) + q4;

    #pragma unroll
    for (int g = 0; g < 4; g++) {
        float4 xr[16];
        #pragma unroll
        for (int c = 0; c < 16; c++) xr[c] = xb[(size_t)(16 * g + c) * 6400];
        #pragma unroll
        for (int o = 0; o < 2; o++) {
            int oc = 2 * g + o;
            float bqv = sb[oc], bkv = sb[8 + oc];
            float4 aq = make_float4(bqv, bqv, bqv, bqv);
            float4 ak = make_float4(bkv, bkv, bkv, bkv);
            #pragma unroll
            for (int c = 0; c < 16; c++) {
                float wqv = swq[oc * 16 + c], wkv = swk[oc * 16 + c];
                aq.x = fmaf(wqv, xr[c].x, aq.x); aq.y = fmaf(wqv, xr[c].y, aq.y);
                aq.z = fmaf(wqv, xr[c].z, aq.z); aq.w = fmaf(wqv, xr[c].w, aq.w);
                ak.x = fmaf(wkv, xr[c].x, ak.x); ak.y = fmaf(wkv, xr[c].y, ak.y);
                ak.z = fmaf(wkv, xr[c].z, ak.z); ak.w = fmaf(wkv, xr[c].w, ak.w);
            }
            ((float4*)g_q)[((size_t)b * NCQ + oc) * 6400 + q4] = aq;
            ((float4*)g_k)[((size_t)b * NCQ + oc) * 6400 + q4] = ak;
        }
        #pragma unroll
        for (int o = 0; o < 16; o++) {
            int oc = 16 * g + o;
            float bv0 = sb[16 + oc];
            float4 av = make_float4(bv0, bv0, bv0, bv0);
            #pragma unroll
            for (int c = 0; c < 16; c++) {
                float wv0 = swv[oc * 16 + c];
                av.x = fmaf(wv0, xr[c].x, av.x); av.y = fmaf(wv0, xr[c].y, av.y);
                av.z = fmaf(wv0, xr[c].z, av.z); av.w = fmaf(wv0, xr[c].w, av.w);
            }
            ((float4*)g_v)[((size_t)b * NC + oc) * 6400 + q4] = av;
        }
    }
}

// ---------------- KT: merged tiled transpose, float4 both sides -------------------
__global__ __launch_bounds__(256) void k_transpose_all()
{
    __shared__ float tile[32][36];
    int z = blockIdx.z;
    const float* src; float* dst; int C, bc;
    if (z < 64)       { src = g_q; dst = g_qT; C = 8;  bc = z; }
    else if (z < 128) { src = g_k; dst = g_kT; C = 8;  bc = z - 64; }
    else              { src = g_v; dst = g_vT; C = 64; bc = z - 128; }
    int b = bc / C, c = bc - b * C;
    int w0 = blockIdx.x * 32, h0 = blockIdx.y * 32;
    int t = threadIdx.x;

    {
        int tx = t & 7, ty = t >> 3;
        float4 v4 = *(const float4*)(src + (size_t)bc * NL + (h0 + ty) * NW + w0 + 4 * tx);
        *(float4*)&tile[ty][4 * tx] = v4;
    }
    __syncthreads();
    {
        int hx = t & 7, wy = t >> 3;
        float4 o;
        o.x = tile[4 * hx + 0][wy];
        o.y = tile[4 * hx + 1][wy];
        o.z = tile[4 * hx + 2][wy];
        o.w = tile[4 * hx + 3][wy];
        size_t daddr = ((size_t)b * NW + (w0 + wy)) * (size_t)(C * NH)
                     + (size_t)c * NH + h0 + 4 * hx;
        *(float4*)&dst[daddr] = o;
    }
}

// ---------------- scalar energy 5x5 (512 thr, 80 rows x 160 cols) -----------------
__device__ __forceinline__ void energy5x5(
    const float* __restrict__ qs, const float* __restrict__ ks,
    int tx, int ty, int row0, float ef[5][5])
{
    #pragma unroll
    for (int i = 0; i < 5; i++)
        #pragma unroll
        for (int j = 0; j < 5; j++) ef[i][j] = 0.f;
    #pragma unroll
    for (int c = 0; c < NCQ; c++) {
        float qv[5], kv[5];
        #pragma unroll
        for (int ii = 0; ii < 5; ii++) qv[ii] = qs[c * PADQ + row0 + ty * 5 + ii];
        #pragma unroll
        for (int jj = 0; jj < 5; jj++) kv[jj] = ks[c * PADQ + tx + 32 * jj];
        #pragma unroll
        for (int ii = 0; ii < 5; ii++)
            #pragma unroll
            for (int jj = 0; jj < 5; jj++) ef[ii][jj] = fmaf(qv[ii], kv[jj], ef[ii][jj]);
    }
}

// ---------------- attv half: 80 rows, warp = 16ch x 20 rows, thread 2c x 5r -------
__device__ __forceinline__ void attv_half(
    const float* __restrict__ E, const float* __restrict__ vs,
    int warp, int lane, float out[2][5])
{
    int cb = (warp & 3) * 16 + (lane & 7);
    int hb = (warp >> 2) * 20 + (lane >> 3) * 5;
    u64 acc[2][5];
    #pragma unroll
    for (int a = 0; a < 2; a++)
        #pragma unroll
        for (int r = 0; r < 5; r++) acc[a][r] = 0ull;
    const float* ap = E + hb * PADE;
    const float* vp = vs + cb * PADV;
    #pragma unroll 2
    for (int pq = 0; pq < 40; pq++) {
        u64 a2[5][2], v2[2][2];
        #pragma unroll
        for (int r = 0; r < 5; r++) {
            float4 f = *(const float4*)(ap + r * PADE + 4 * pq);
            a2[r][0] = pack2(f.x, f.y); a2[r][1] = pack2(f.z, f.w);
        }
        #pragma unroll
        for (int a = 0; a < 2; a++) {
            float4 g = *(const float4*)(vp + a * (8 * PADV) + 4 * pq);
            v2[a][0] = pack2(g.x, g.y); v2[a][1] = pack2(g.z, g.w);
        }
        #pragma unroll
        for (int a = 0; a < 2; a++)
            #pragma unroll
            for (int r = 0; r < 5; r++) {
                ffma2(acc[a][r], v2[a][0], a2[r][0]);
                ffma2(acc[a][r], v2[a][1], a2[r][1]);
            }
    }
    #pragma unroll
    for (int a = 0; a < 2; a++)
        #pragma unroll
        for (int r = 0; r < 5; r++) {
            float2 s = unpack2(acc[a][r]);
            out[a][r] = s.x + s.y;
        }
}

// smem layout for half kernels (floats): qs 1296 | ks 1296 | E 80*164 | vs 64*164
#define OFF_KS 1296
#define OFF_E  2592
#define OFF_VS 15712
#define DYN_HALF ((2592 + 80 * PADE + 64 * PADV) * 4)   // 104,832 B

// ---------------- K3a: per (b,w,half) — E_H, LOCAL softmax, att_H~, out_H~ --------
__global__ __launch_bounds__(512, 2) void k_colpass()
{
    extern __shared__ __align__(16) float sm[];
    float* qs = sm;
    float* ks = sm + OFF_KS;
    float* E  = sm + OFF_E;
    float* vs = sm + OFF_VS;
    int t = threadIdx.x;
    int bidx = blockIdx.x;
    int half = blockIdx.y;
    int b = bidx / NW, w = bidx - b * NW;
    int row0 = half * 80;
    int tx = t & 31, ty = t >> 5;

    {
        const float2* gq2 = (const float2*)g_qT;
        const float2* gk2 = (const float2*)g_kT;
        const float2* gv2 = (const float2*)g_vT;
        int base2 = bidx * 640;
        for (int i2 = t; i2 < 640; i2 += 512) {
            int c = i2 / 80, j2 = i2 - c * 80;
            *(float2*)&qs[c * PADQ + 2 * j2] = gq2[base2 + i2];
            *(float2*)&ks[c * PADQ + 2 * j2] = gk2[base2 + i2];
        }
        int vb2 = bidx * 5120;
        for (int i2 = t; i2 < 5120; i2 += 512) {
            int c = i2 / 80, j2 = i2 - c * 80;
            *(float2*)&vs[c * PADV + 2 * j2] = gv2[vb2 + i2];
        }
    }
    __syncthreads();

    float ef[5][5];
    energy5x5(qs, ks, tx, ty, row0, ef);

    // LOCAL softmax per row h: mask diag, compute (mH, sH), write exp(e-mH) UNNORMALIZED
    #pragma unroll
    for (int ii = 0; ii < 5; ii++) {
        int hh = ty * 5 + ii;
        int h  = row0 + hh;
        float m = -3.0e38f;
        #pragma unroll
        for (int jj = 0; jj < 5; jj++) {
            int j = tx + 32 * jj;
            if (j == h) ef[ii][jj] = -1.0e30f;
            m = fmaxf(m, ef[ii][jj]);
        }
        REDMAX32(m);
        float s = 0.f;
        #pragma unroll
        for (int jj = 0; jj < 5; jj++) {
            ef[ii][jj] = __expf(ef[ii][jj] - m);
            s += ef[ii][jj];
        }
        REDSUM32(s);
        if (tx == 0) {
            g_mH[bidx * NH + h] = m;
            g_sH[bidx * NH + h] = s;
        }
        #pragma unroll
        for (int jj = 0; jj < 5; jj++)
            E[hh * PADE + tx + 32 * jj] = ef[ii][jj];
    }
    __syncthreads();

    int warp = t >> 5, lane = t & 31;
    float out[2][5];
    attv_half(E, vs, warp, lane, out);
    __syncthreads();

    // stage [hh][c] (pad 68) then float4 write to g_outH[b][row0+hh][w][c]
    {
        int cb = (warp & 3) * 16 + (lane & 7);
        int hb = (warp >> 2) * 20 + (lane >> 3) * 5;
        #pragma unroll
        for (int a = 0; a < 2; a++)
            #pragma unroll
            for (int r = 0; r < 5; r++)
                E[(hb + r) * PADS + cb + 8 * a] = out[a][r];
    }
    __syncthreads();
    for (int i4 = t; i4 < 80 * 16; i4 += 512) {
        int hh = i4 >> 4, c4 = i4 & 15;
        *(float4*)&g_outH[(((size_t)b * NH + row0 + hh) * NW + w) * NC + 4 * c4] =
            *(float4*)&E[hh * PADS + 4 * c4];
    }
}

// ---------------- K3b: per (b,h,half) — E_W, local stats, merge, conv, BN ---------
__global__ __launch_bounds__(512, 2) void k_rowpass(
    const float* __restrict__ gamma, const float* __restrict__ w1d)
{
    extern __shared__ __align__(16) float sm[];
    __shared__ float sw1[1024];
    __shared__ float csum[NC], csq[NC];
    __shared__ float scH[80], scW[80];     // per-wl combine scales
    float* qs = sm;
    float* ks = sm + OFF_KS;
    float* E  = sm + OFF_E;
    float* vs = sm + OFF_VS;
    int t = threadIdx.x;
    int bidx = blockIdx.x;
    int half = blockIdx.y;
    int b = bidx / NH, h = bidx - b * NH;
    int row0 = half * 80;
    int tx = t & 31, ty = t >> 5;

    // prefetch colpass local stats (broadcast loads) before the energy matmul
    float mHr[5], sHr[5];
    #pragma unroll
    for (int ii = 0; ii < 5; ii++) {
        int wg = row0 + ty * 5 + ii;
        mHr[ii] = g_mH[(b * NW + wg) * NH + h];
        sHr[ii] = g_sH[(b * NW + wg) * NH + h];
    }

    for (int i = t; i < 1024; i += 512) sw1[i] = w1d[i];
    if (t < NC) { csum[t] = 0.f; csq[t] = 0.f; }
    {
        const float2* gq2 = (const float2*)g_q;
        const float2* gk2 = (const float2*)g_k;
        const float2* gv2 = (const float2*)g_v;
        int base2 = (b * NCQ * NL + h * NW) >> 1;
        for (int i2 = t; i2 < NCQ * 80; i2 += 512) {
            int c = i2 / 80, j2 = i2 - c * 80;
            *(float2*)&qs[c * PADQ + 2 * j2] = gq2[base2 + c * (NL >> 1) + j2];
            *(float2*)&ks[c * PADQ + 2 * j2] = gk2[base2 + c * (NL >> 1) + j2];
        }
        int vbase2 = (b * NC * NL + h * NW) >> 1;
        for (int i2 = t; i2 < NC * 80; i2 += 512) {
            int c = i2 / 80, j2 = i2 - c * 80;
            *(float2*)&vs[c * PADV + 2 * j2] = gv2[vbase2 + c * (NL >> 1) + j2];
        }
    }
    __syncthreads();

    float ef[5][5];
    energy5x5(qs, ks, tx, ty, row0, ef);

    // local E_W stats per row wl, merge with (mH, sH), write exp(e-mW) unnormalized
    #pragma unroll
    for (int ii = 0; ii < 5; ii++) {
        int wl = ty * 5 + ii;
        float m = -3.0e38f;
        #pragma unroll
        for (int jj = 0; jj < 5; jj++) m = fmaxf(m, ef[ii][jj]);
        REDMAX32(m);
        float s = 0.f;
        #pragma unroll
        for (int jj = 0; jj < 5; jj++) {
            ef[ii][jj] = __expf(ef[ii][jj] - m);
            s += ef[ii][jj];
        }
        REDSUM32(s);
        if (tx == 0) {
            float mH = mHr[ii], sH = sHr[ii];
            float M  = fmaxf(mH, m);
            float aH = __expf(mH - M), aW = __expf(m - M);
            float Zi = 1.f / (sH * aH + s * aW);
            scH[wl] = aH * Zi;
            scW[wl] = aW * Zi;
        }
        #pragma unroll
        for (int jj = 0; jj < 5; jj++)
            E[wl * PADE + tx + 32 * jj] = ef[ii][jj];
    }
    __syncthreads();

    int warp = t >> 5, lane = t & 31;
    float ow[2][5];
    attv_half(E, vs, warp, lane, ow);
    float gm = gamma[0];
    __syncthreads();

    // load out_H~ slab for this half's w rows (float4), staged [wl][c] pad 68
    {
        const float4* goh4 = (const float4*)(g_outH + (((size_t)b * NH + h) * NW + row0) * NC);
        for (int i4 = t; i4 < 80 * 16; i4 += 512) {
            int wl = i4 >> 4, c4 = i4 & 15;
            *(float4*)&E[wl * PADS + 4 * c4] = goh4[i4];
        }
    }
    __syncthreads();

    // combine into conv-input vs[c][wl]: gamma*(out_W~*scW + out_H~*scH)
    {
        int cb = (warp & 3) * 16 + (lane & 7);
        int hb = (warp >> 2) * 20 + (lane >> 3) * 5;
        #pragma unroll
        for (int a = 0; a < 2; a++)
            #pragma unroll
            for (int r = 0; r < 5; r++) {
                int c = cb + 8 * a, wl = hb + r;
                vs[c * PADV + wl] = gm * (ow[a][r] * scW[wl] + E[wl * PADS + c] * scH[wl]);
            }
    }
    __syncthreads();

    // grouped conv: thread owns oc-pair (2p, 2p+1) x 5 wl; data LDS shared by both
    {
        int p = t >> 4, lane16 = t & 15;
        int oc0 = 2 * p;
        int g = p >> 3;                       // = oc0 >> 4
        const float* wv0 = &sw1[oc0 * 16];
        const float* wv1 = &sw1[oc0 * 16 + 16];
        float s0 = 0.f, q20 = 0.f, s1 = 0.f, q21 = 0.f;
        size_t ob = ((size_t)b * NC + oc0) * NL + h * NW + row0;
        #pragma unroll
        for (int k = 0; k < 5; k++) {
            int wl = lane16 + 16 * k;
            float a0 = 0.f, a1 = 0.f;
            #pragma unroll
            for (int c = 0; c < 16; c++) {
                float xv = vs[(16 * g + c) * PADV + wl];
                a0 = fmaf(wv0[c], xv, a0);
                a1 = fmaf(wv1[c], xv, a1);
            }
            g_o[ob + wl]      = a0;
            g_o[ob + NL + wl] = a1;
            s0 += a0; q20 += a0 * a0;
            s1 += a1; q21 += a1 * a1;
        }
        // reduce over the 16 lanes sharing this oc-pair
        #pragma unroll
        for (int off = 8; off > 0; off >>= 1) {
            s0  += __shfl_xor_sync(0xffffffffu, s0, off);
            q20 += __shfl_xor_sync(0xffffffffu, q20, off);
            s1  += __shfl_xor_sync(0xffffffffu, s1, off);
            q21 += __shfl_xor_sync(0xffffffffu, q21, off);
        }
        if (lane16 == 0) {
            atomicAdd(&csum[oc0], s0);     atomicAdd(&csq[oc0], q20);
            atomicAdd(&csum[oc0 + 1], s1); atomicAdd(&csq[oc0 + 1], q21);
        }
    }
    __syncthreads();
    if (t < NC) { atomicAdd(&g_sum[t], csum[t]); atomicAdd(&g_sumsq[t], csq[t]); }
}

// ---------------- K4: finalize BN scale/shift -------------------------------------
__global__ void k_bnfin(const float* __restrict__ bn_w, const float* __restrict__ bn_b)
{
    int c = threadIdx.x;
    const float invN = 1.f / (float)(NB * NL);
    float mean = g_sum[c] * invN;
    float var  = g_sumsq[c] * invN - mean * mean;
    float a    = bn_w[c] * rsqrtf(var + 1e-5f);
    g_bna[c] = a;
    g_bnb[c] = bn_b[c] - mean * a;
}

// ---------------- K5: BN apply + residual + ReLU (float4) -------------------------
__global__ __launch_bounds__(256) void k_final(const float* __restrict__ x, float* __restrict__ out)
{
    int i = blockIdx.x * 256 + threadIdx.x;
    int c = (i / 6400) & 63;
    float a = g_bna[c], bb = g_bnb[c];
    float4 o = ((const float4*)g_o)[i];
    float4 xv = ((const float4*)x)[i];
    float4 r;
    r.x = fmaf(o.x, a, bb) + xv.x; r.x = r.x > 0.f ? r.x : 0.f;
    r.y = fmaf(o.y, a, bb) + xv.y; r.y = r.y > 0.f ? r.y : 0.f;
    r.z = fmaf(o.z, a, bb) + xv.z; r.z = r.z > 0.f ? r.z : 0.f;
    r.w = fmaf(o.w, a, bb) + xv.w; r.w = r.w > 0.f ? r.w : 0.f;
    ((float4*)out)[i] = r;
}

// ---------------- host ------------------------------------------------------------
extern "C" void kernel_launch(void* const* d_in, const int* in_sizes, int n_in,
                              void* d_out, int out_size)
{
    (void)in_sizes; (void)n_in; (void)out_size;
    const float* x     = (const float*)d_in[0];
    const float* wq    = (const float*)d_in[1];
    const float* bq    = (const float*)d_in[2];
    const float* wk    = (const float*)d_in[3];
    const float* bk    = (const float*)d_in[4];
    const float* wv    = (const float*)d_in[5];
    const float* bv    = (const float*)d_in[6];
    const float* gamma = (const float*)d_in[7];
    const float* w1d   = (const float*)d_in[8];
    const float* bn_w  = (const float*)d_in[9];
    const float* bn_b  = (const float*)d_in[10];
    float* out = (float*)d_out;

    cudaFuncSetAttribute(k_colpass, cudaFuncAttributeMaxDynamicSharedMemorySize, DYN_HALF);
    cudaFuncSetAttribute(k_rowpass, cudaFuncAttributeMaxDynamicSharedMemorySize, DYN_HALF);

    k_qkv<<<400, 128>>>(x, wq, bq, wk, bk, wv, bv);                 // 0
    k_transpose_all<<<dim3(5, 5, 640), 256>>>();                    // 1
    k_colpass<<<dim3(NB * NW, 2), 512, DYN_HALF>>>();               // 2
    k_rowpass<<<dim3(NB * NH, 2), 512, DYN_HALF>>>(gamma, w1d);     // 3
    k_bnfin<<<1, 64>>>(bn_w, bn_b);                                 // 4
    k_final<<<(NB * NC * NL) / 1024, 256>>>(x, out);                // 5
}